// round 1
// baseline (speedup 1.0000x reference)
#include <cuda_runtime.h>
#include <cuda_bf16.h>
#include <cstdint>

// ---------------------------------------------------------------------------
// BinConv (3x3, pad1) + bias + ReLU + eval BatchNorm, exact via int8 IMMA.
//   xb,wb in {-1,+1} -> int8; padding -> 0 (contributes 0 to dot, exact).
//   conv = s32 accum; y = relu(conv + b) * scale + shift,
//   scale = gamma*rsqrt(var+eps), shift = beta - mean*scale.
// ---------------------------------------------------------------------------

#define N_IMG 16
#define CIN   64
#define COUT  64
#define HDIM  256
#define WDIM  256
#define HP    258   // padded
#define WP    258

// Padded NHWC binarized activations. Zero-initialized at module load =>
// borders are permanent zeros (conv padding). Interior rewritten each call.
__device__ __align__(16) signed char g_xpad[(size_t)N_IMG * HP * WP * CIN];
// Binarized weights: g_B[cout][k], k = (dy*3+dx)*64 + c
__device__ __align__(16) signed char g_B[COUT * 576];
__device__ float g_scale[COUT];
__device__ float g_shift[COUT];

// ---------------------------------------------------------------------------
// Prep 1: binarize x (NCHW f32) -> g_xpad (padded NHWC int8). Tiled transpose.
// grid (W/64, H, N), block 256.
// ---------------------------------------------------------------------------
__global__ void k_binx(const float* __restrict__ x) {
    __shared__ signed char s[64 * 68];   // [w][c], stride 68 (conflict-free)
    const int n = blockIdx.z, h = blockIdx.y, w0 = blockIdx.x * 64;
    const int tid = threadIdx.x;

    // Phase 1: coalesced read along w for each channel, binarize into smem.
    const int w  = tid & 63;
    const int cb = tid >> 6;             // 0..3
    const float* xp = x + (((size_t)n * CIN) * HDIM + h) * WDIM + w0 + w;
#pragma unroll
    for (int ci = 0; ci < 16; ci++) {
        int c = cb + ci * 4;
        float v = xp[(size_t)c * (HDIM * WDIM)];
        s[w * 68 + c] = (v >= 0.0f) ? (signed char)1 : (signed char)-1;
    }
    __syncthreads();

    // Phase 2: write NHWC, 128 contiguous bytes per warp.
    const int c4  = tid & 15;
    const int wp0 = tid >> 4;            // 0..15
    signed char* dst = g_xpad + (((size_t)n * HP + (h + 1)) * WP + (w0 + 1)) * CIN;
#pragma unroll
    for (int it = 0; it < 4; it++) {
        int wp = wp0 + it * 16;
        unsigned int v = *(const unsigned int*)(s + wp * 68 + c4 * 4);
        *(unsigned int*)(dst + wp * CIN + c4 * 4) = v;
    }
}

// ---------------------------------------------------------------------------
// Prep 2: binarize weights + BN constants. grid 36, block 1024 (exact 36864).
// ---------------------------------------------------------------------------
__global__ void k_binw(const float* __restrict__ w,
                       const float* __restrict__ gamma,
                       const float* __restrict__ beta,
                       const float* __restrict__ mean,
                       const float* __restrict__ var) {
    int idx = blockIdx.x * blockDim.x + threadIdx.x;
    if (idx < COUT * 576) {
        int cout = idx / 576;
        int k    = idx - cout * 576;
        int tap  = k >> 6;               // dy*3+dx
        int c    = k & 63;
        float v = w[((size_t)cout * CIN + c) * 9 + tap];
        g_B[cout * 576 + k] = (v >= 0.0f) ? (signed char)1 : (signed char)-1;
    }
    if (blockIdx.x == 0 && threadIdx.x < COUT) {
        int c = threadIdx.x;
        float inv = gamma[c] * rsqrtf(var[c] + 1e-5f);
        g_scale[c] = inv;
        g_shift[c] = beta[c] - mean[c] * inv;
    }
}

// ---------------------------------------------------------------------------
// Main: implicit-GEMM int8 IMMA.
// CTA = (n, h, 128 w-pixels) x all 64 couts. 8 warps in 4(m) x 2(n) grid,
// each warp a 32x32 output tile via m16n8k32 s8 mma.
// ---------------------------------------------------------------------------
#define XS_W_STRIDE 80     // bytes per w-position in smem A (64 data + 16 pad)
#define BS_STRIDE   592    // bytes per cout in smem B (576 data + 16 pad)
#define XS_OFF 768
#define BS_OFF (XS_OFF + 3 * 130 * XS_W_STRIDE)      // 768 + 31200 = 31968
#define SMEM_TOTAL (BS_OFF + COUT * BS_STRIDE)       // 31968 + 37888 = 69856

extern __shared__ char sm_dyn[];

__device__ __forceinline__ void mma_s8(int* d, const unsigned int* a,
                                       unsigned int b0, unsigned int b1) {
    asm volatile(
        "mma.sync.aligned.m16n8k32.row.col.s32.s8.s8.s32 "
        "{%0,%1,%2,%3}, {%4,%5,%6,%7}, {%8,%9}, {%0,%1,%2,%3};\n"
        : "+r"(d[0]), "+r"(d[1]), "+r"(d[2]), "+r"(d[3])
        : "r"(a[0]), "r"(a[1]), "r"(a[2]), "r"(a[3]), "r"(b0), "r"(b1));
}

__global__ __launch_bounds__(256)
void k_main(const float* __restrict__ bias, float* __restrict__ out) {
    float* s_bias  = (float*)(sm_dyn);
    float* s_scale = (float*)(sm_dyn + 256);
    float* s_shift = (float*)(sm_dyn + 512);
    signed char* xs = (signed char*)(sm_dyn + XS_OFF);
    signed char* Bs = (signed char*)(sm_dyn + BS_OFF);

    const int tid = threadIdx.x;
    const int n = blockIdx.z, h = blockIdx.y, w0 = blockIdx.x * 128;

    if (tid < COUT) {
        s_bias[tid]  = bias[tid];
        s_scale[tid] = g_scale[tid];
        s_shift[tid] = g_shift[tid];
    }

    // Load A halo: 3 rows x 130 w x 64 c from padded NHWC (contiguous src).
    const signed char* xg = g_xpad + (((size_t)n * HP + h) * WP + w0) * CIN;
    for (int t = tid; t < 390 * 4; t += 256) {
        int wrow = t >> 2, j = t & 3;
        int dy = wrow / 130, i = wrow - dy * 130;
        uint4 v = *(const uint4*)(xg + ((size_t)dy * WP + i) * CIN + j * 16);
        *(uint4*)(xs + wrow * XS_W_STRIDE + j * 16) = v;
    }
    // Load B: 64 couts x 576.
    for (int t = tid; t < 64 * 36; t += 256) {
        int co = t / 36, j = t - co * 36;
        uint4 v = *(const uint4*)(g_B + co * 576 + j * 16);
        *(uint4*)(Bs + co * BS_STRIDE + j * 16) = v;
    }
    __syncthreads();

    const int lane = tid & 31;
    const int quad = lane >> 2;   // 0..7
    const int qid  = lane & 3;    // 0..3
    const int wid  = tid >> 5;
    const int m0   = (wid & 3) * 32;   // pixel base for this warp
    const int n0   = (wid >> 2) * 32;  // cout  base for this warp

    int acc[2][4][4];
#pragma unroll
    for (int i = 0; i < 2; i++)
#pragma unroll
        for (int j = 0; j < 4; j++)
#pragma unroll
            for (int r = 0; r < 4; r++) acc[i][j][r] = 0;

#pragma unroll
    for (int dy = 0; dy < 3; dy++) {
#pragma unroll
        for (int dx = 0; dx < 3; dx++) {
            const int kbase = (dy * 3 + dx) * 64;
#pragma unroll
            for (int ks = 0; ks < 64; ks += 32) {
                unsigned int a[2][4];
#pragma unroll
                for (int i = 0; i < 2; i++) {
                    int p = m0 + i * 16 + quad;
                    const signed char* ap =
                        xs + (dy * 130 + p + dx) * XS_W_STRIDE + ks + qid * 4;
                    a[i][0] = *(const unsigned int*)(ap);
                    a[i][2] = *(const unsigned int*)(ap + 16);
                    a[i][1] = *(const unsigned int*)(ap + 8 * XS_W_STRIDE);
                    a[i][3] = *(const unsigned int*)(ap + 8 * XS_W_STRIDE + 16);
                }
                const int kk = kbase + ks;
#pragma unroll
                for (int j = 0; j < 4; j++) {
                    int cout = n0 + j * 8 + quad;
                    const signed char* bp = Bs + cout * BS_STRIDE + kk + qid * 4;
                    unsigned int b0 = *(const unsigned int*)(bp);
                    unsigned int b1 = *(const unsigned int*)(bp + 16);
                    mma_s8(acc[0][j], a[0], b0, b1);
                    mma_s8(acc[1][j], a[1], b0, b1);
                }
            }
        }
    }

    // Epilogue: bias + relu + BN, transpose in smem, coalesced float4 stores.
    __syncthreads();
    float* s_out = (float*)(sm_dyn + XS_OFF);  // [cout][128], stride 132
#pragma unroll
    for (int i = 0; i < 2; i++) {
#pragma unroll
        for (int j = 0; j < 4; j++) {
#pragma unroll
            for (int r = 0; r < 4; r++) {
                int row = m0 + i * 16 + quad + ((r & 2) ? 8 : 0);
                int col = n0 + j * 8 + qid * 2 + (r & 1);
                float f = (float)acc[i][j][r] + s_bias[col];
                f = fmaxf(f, 0.0f);
                s_out[col * 132 + row] = fmaf(f, s_scale[col], s_shift[col]);
            }
        }
    }
    __syncthreads();

    for (int t = tid; t < 2048; t += 256) {
        int co = t >> 5, m4 = t & 31;
        float4 v = *(const float4*)(s_out + co * 132 + m4 * 4);
        size_t o = (((size_t)n * COUT + co) * HDIM + h) * WDIM + w0 + m4 * 4;
        *(float4*)(out + o) = v;
    }
}

// ---------------------------------------------------------------------------
extern "C" void kernel_launch(void* const* d_in, const int* in_sizes, int n_in,
                              void* d_out, int out_size) {
    const float* x     = (const float*)d_in[0];
    const float* w     = (const float*)d_in[1];
    const float* b     = (const float*)d_in[2];
    const float* gamma = (const float*)d_in[3];
    const float* beta  = (const float*)d_in[4];
    const float* mean  = (const float*)d_in[5];
    const float* var   = (const float*)d_in[6];
    float* out = (float*)d_out;

    cudaFuncSetAttribute(k_main, cudaFuncAttributeMaxDynamicSharedMemorySize,
                         SMEM_TOTAL);

    dim3 g1(WDIM / 64, HDIM, N_IMG);
    k_binx<<<g1, 256>>>(x);

    k_binw<<<36, 1024>>>(w, gamma, beta, mean, var);

    dim3 g2(WDIM / 128, HDIM, N_IMG);
    k_main<<<g2, 256, SMEM_TOTAL>>>(b, out);
}